// round 3
// baseline (speedup 1.0000x reference)
#include <cuda_runtime.h>
#include <math.h>

#define Nn      65536
#define Mm      256
#define Hh      4
#define CTRLD   1024
#define LSTMIN  3072
#define OUTD    2048
#define EPSF    1e-8f

#define PGRID   512
#define PBLK    256
#define ROWS_B  (Nn / PGRID)      // 128 rows per block
#define ROWS_W  (ROWS_B / 8)      // 16 rows per warp

// ---------------- scratch (__device__ globals) ----------------
__device__ float g_mem[(size_t)Nn * Mm];   // working memory copy (64MB)
__device__ float g_simw[Nn];
__device__ float g_simr[Nn];
__device__ float g_wshw[Nn];
__device__ float g_wshr[Nn];
__device__ float g_gates[3 * CTRLD];
__device__ float g_ctrl[CTRLD];
__device__ float g_o[Hh * 1036];
__device__ float g_kw[Hh * Mm];
__device__ float g_kr[Hh * Mm];
__device__ float g_e [Hh * Mm];
__device__ float g_a [Hh * Mm];
__device__ float g_sc[80];
__device__ float g_S [32];
__device__ float g_reads[Hh * Mm];
__device__ unsigned long long g_barcnt;
__device__ int g_done_gates;
__device__ int g_done_fc;

// ---------------- helpers ----------------
__device__ __forceinline__ float warpSum(float v) {
#pragma unroll
    for (int o = 16; o; o >>= 1) v += __shfl_down_sync(0xffffffffu, v, o);
    return v;
}
__device__ __forceinline__ float blockSum(float v) {
    __shared__ float sh[32];
    int lane = threadIdx.x & 31, wid = threadIdx.x >> 5;
    v = warpSum(v);
    if (lane == 0) sh[wid] = v;
    __syncthreads();
    int nw = (blockDim.x + 31) >> 5;
    v = (threadIdx.x < nw) ? sh[threadIdx.x] : 0.f;
    if (wid == 0) v = warpSum(v);
    __syncthreads();
    return v;
}
__device__ __forceinline__ float sigmoidf(float x) { return 1.f / (1.f + expf(-x)); }
__device__ __forceinline__ float softplusf(float x) {
    return x > 0.f ? x + log1pf(expf(-x)) : log1pf(expf(x));
}
__device__ __forceinline__ float dot4(float4 a, float4 b) {
    return a.x*b.x + a.y*b.y + a.z*b.z + a.w*b.w;
}
__device__ __forceinline__ void gridbar(unsigned long long base, int idx) {
    __syncthreads();
    if (threadIdx.x == 0) {
        __threadfence();
        atomicAdd(&g_barcnt, 1ULL);
        unsigned long long target = base + (unsigned long long)idx * gridDim.x;
        while (*(volatile unsigned long long*)&g_barcnt < target) __nanosleep(32);
    }
    __syncthreads();
}

// ---------------- 1) LSTM gates GEMV (warp-per-row) + last-block cell state ------
__global__ void __launch_bounds__(256) k_gates(
    const float* __restrict__ x, const float* __restrict__ prev_reads,
    const float* __restrict__ prev_h, const float* __restrict__ prev_c,
    const float* __restrict__ W_ih, const float* __restrict__ W_hh,
    const float* __restrict__ b_lstm) {
    __shared__ float s_in[4096];           // [x(2048); prev_reads(1024); prev_h(1024)]
    int t = threadIdx.x;
    float4* si4 = (float4*)s_in;
    for (int j = t; j < 512; j += 256) si4[j] = ((const float4*)x)[j];
    if (t < 256) si4[512 + t] = ((const float4*)prev_reads)[t];
    if (t < 256) si4[768 + t] = ((const float4*)prev_h)[t];
    __syncthreads();
    int wrp = t >> 5, lane = t & 31;
    int row = blockIdx.x * 8 + wrp;        // 0..3071
    const float4* wa = (const float4*)(W_ih + (size_t)row * LSTMIN);
    const float4* wh = (const float4*)(W_hh + (size_t)row * CTRLD);
    float s = 0.f;
#pragma unroll 8
    for (int j = lane; j < 768; j += 32) s += dot4(wa[j], si4[j]);
#pragma unroll 8
    for (int j = lane; j < 256; j += 32) s += dot4(wh[j], si4[768 + j]);
    s = warpSum(s);
    if (lane == 0) g_gates[row] = s + b_lstm[row];
    __threadfence();
    __syncthreads();
    __shared__ int s_last;
    if (t == 0) {
        int d = atomicAdd(&g_done_gates, 1);
        s_last = (d == (int)gridDim.x - 1);
        if (s_last) g_done_gates = 0;
    }
    __syncthreads();
    if (s_last) {
        for (int j = t; j < CTRLD; j += 256) {
            float ig = g_gates[j], fg = g_gates[CTRLD + j], gg = g_gates[2 * CTRLD + j];
            g_ctrl[j] = sigmoidf(fg) * prev_c[j] + sigmoidf(ig) * tanhf(gg);
            g_reads[j] = 0.f;
        }
        if (t < 32) g_S[t] = 0.f;
    }
}

// ---------------- 2) head FCs (warp-per-row) + last-block derive ------------------
__global__ void __launch_bounds__(256) k_headfc(
    const float* __restrict__ Ww, const float* __restrict__ bw,
    const float* __restrict__ Wr, const float* __restrict__ br) {
    __shared__ float s_c[CTRLD];
    int t = threadIdx.x;
    if (t < 256) ((float4*)s_c)[t] = ((const float4*)g_ctrl)[t];
    __syncthreads();
    int wrp = t >> 5, lane = t & 31;
    int row = blockIdx.x * 8 + wrp;        // 0..4143
    int hd = row / 1036, k = row % 1036;
    const float* wrow; float bias;
    if (k < 774) { wrow = Ww + ((size_t)hd * 774 + k) * CTRLD; bias = bw[hd * 774 + k]; }
    else         { int kk = k - 774; wrow = Wr + ((size_t)hd * 262 + kk) * CTRLD; bias = br[hd * 262 + kk]; }
    const float4* w4 = (const float4*)wrow;
    const float4* c4 = (const float4*)s_c;
    float s = 0.f;
#pragma unroll 8
    for (int j = lane; j < 256; j += 32) s += dot4(w4[j], c4[j]);
    s = warpSum(s);
    if (lane == 0) g_o[row] = s + bias;
    __threadfence();
    __syncthreads();
    __shared__ int s_last;
    if (t == 0) {
        int d = atomicAdd(&g_done_fc, 1);
        s_last = (d == (int)gridDim.x - 1);
        if (s_last) g_done_fc = 0;
    }
    __syncthreads();
    if (s_last) {
        for (int b = 0; b < 8; b++) {
            int hh = b >> 1, role = b & 1;
            const float* o = g_o + hh * 1036 + (role ? 774 : 0);
            float ssl = 0.f;
            for (int j = t; j < Mm; j += 256) {
                float kv = tanhf(o[j]);
                (role ? g_kr : g_kw)[hh * Mm + j] = kv;
                ssl += kv * kv;
                if (!role) {
                    g_e[hh * Mm + j] = sigmoidf(o[262 + j]);
                    g_a[hh * Mm + j] = tanhf(o[518 + j]);
                }
            }
            float ss = blockSum(ssl);
            if (t == 0) {
                float* sc = g_sc + b * 8;
                sc[0] = softplusf(o[256]);
                sc[1] = sigmoidf(o[257]);
                float s0 = o[258], s1 = o[259], s2 = o[260];
                float mx = fmaxf(s0, fmaxf(s1, s2));
                float e0 = expf(s0 - mx), e1 = expf(s1 - mx), e2 = expf(s2 - mx);
                float es = e0 + e1 + e2;
                sc[2] = e0 / es; sc[3] = e1 / es; sc[4] = e2 / es;
                sc[5] = 1.f + softplusf(o[261]);
                sc[6] = sqrtf(ss);
            }
        }
    }
}

// ---------------- addressing phase --------------------------------------------------
__device__ __forceinline__ void addr_phase(int b, int t, int hr, int hw,
                                           const float* __restrict__ prev_rw,
                                           const float* __restrict__ prev_ww) {
    float sumr = 0.f, sumw = 0.f;
    if (t < ROWS_B) {
        int i = b * ROWS_B + t;
        int ip = (i + 1) & (Nn - 1), im = (i - 1) & (Nn - 1);
        if (hr >= 0) {
            const float* sc = g_sc + (hr * 2 + 1) * 8;
            float beta = sc[0], gg = sc[1], c0 = sc[2], c1 = sc[3], c2 = sc[4], gamma = sc[5];
            float gS = gg / __ldcg(&g_S[hr * 4 + 2]);
            float om = 1.f - gg;
            const float* pw = prev_rw + (size_t)hr * Nn;
            float wgp = gS * expf(beta * __ldcg(&g_simr[ip])) + om * pw[ip];
            float wgc = gS * expf(beta * __ldcg(&g_simr[i]))  + om * pw[i];
            float wgm = gS * expf(beta * __ldcg(&g_simr[im])) + om * pw[im];
            float ws = c0 * wgp + c1 * wgc + c2 * wgm;
            float wsh = powf(fmaxf(ws, 1e-12f), gamma);
            g_wshr[i] = wsh; sumr = wsh;
        }
        if (hw >= 0) {
            const float* sc = g_sc + (hw * 2) * 8;
            float beta = sc[0], gg = sc[1], c0 = sc[2], c1 = sc[3], c2 = sc[4], gamma = sc[5];
            float gS = gg / __ldcg(&g_S[hw * 4 + 0]);
            float om = 1.f - gg;
            const float* pw = prev_ww + (size_t)hw * Nn;
            float wgp = gS * expf(beta * __ldcg(&g_simw[ip])) + om * pw[ip];
            float wgc = gS * expf(beta * __ldcg(&g_simw[i]))  + om * pw[i];
            float wgm = gS * expf(beta * __ldcg(&g_simw[im])) + om * pw[im];
            float ws = c0 * wgp + c1 * wgc + c2 * wgm;
            float wsh = powf(fmaxf(ws, 1e-12f), gamma);
            g_wshw[i] = wsh; sumw = wsh;
        }
    }
    sumr = blockSum(sumr);
    if (t == 0 && hr >= 0) atomicAdd(&g_S[hr * 4 + 3], sumr);
    sumw = blockSum(sumw);
    if (t == 0 && hw >= 0) atomicAdd(&g_S[hw * 4 + 1], sumw);
}

// ---------------- 3) persistent memory pipeline + fused output GEMV -----------------
__global__ void __launch_bounds__(PBLK, 4) k_persist(
    const float* __restrict__ mem_in,
    const float* __restrict__ prev_rw,
    const float* __restrict__ prev_ww,
    const float* __restrict__ W_out,
    const float* __restrict__ b_out,
    float* __restrict__ out) {
    __shared__ float s_e[Mm], s_a[Mm], s_kr[Mm], s_kw[Mm];
    __shared__ float s_acc[Mm];
    __shared__ float s_rd[CTRLD];
    __shared__ float s_red[16];
    __shared__ unsigned long long s_base;
    const int b = blockIdx.x, t = threadIdx.x, lane = t & 31, wrp = t >> 5;
    const int r0 = b * ROWS_B;
    const int rbase = r0 + wrp * ROWS_W;

    if (t == 0) s_base = *(volatile unsigned long long*)&g_barcnt;
    s_kw[t] = g_kw[t];
    __syncthreads();
    const unsigned long long base = s_base;

    // ---- pass0: sim for head-0 write key (prefetched) ----
    {
        float beta = g_sc[0], kn = g_sc[6];
        float ess = 0.f;
        const float4* k4 = (const float4*)s_kw;
        float4 k0 = k4[lane], k1 = k4[lane + 32];
        const float4* row = (const float4*)(mem_in + (size_t)rbase * Mm);
        float4 m0 = row[lane], m1 = row[lane + 32];
        for (int k = 0; k < ROWS_W; k++) {
            float4 n0, n1;
            if (k + 1 < ROWS_W) {
                const float4* nrow = (const float4*)(mem_in + (size_t)(rbase + k + 1) * Mm);
                n0 = nrow[lane]; n1 = nrow[lane + 32];
            }
            float dot = dot4(m0, k0) + dot4(m1, k1);
            float ss  = dot4(m0, m0) + dot4(m1, m1);
            dot = warpSum(dot); ss = warpSum(ss);
            if (lane == 0) {
                float sim = dot / (sqrtf(ss) * kn + EPSF);
                g_simw[rbase + k] = sim;
                ess += expf(beta * sim);
            }
            m0 = n0; m1 = n1;
        }
        if (lane == 0) s_red[wrp] = ess;
        __syncthreads();
        if (t == 0) { float s = 0.f; for (int w = 0; w < 8; w++) s += s_red[w]; atomicAdd(&g_S[0], s); }
    }
    gridbar(base, 1);
    addr_phase(b, t, -1, 0, prev_rw, prev_ww);
    gridbar(base, 2);

    for (int hd = 0; hd < 4; hd++) {
        __syncthreads();
        s_e[t]  = g_e[hd * Mm + t];
        s_a[t]  = g_a[hd * Mm + t];
        s_kr[t] = g_kr[hd * Mm + t];
        s_kw[t] = g_kw[((hd + 1) & 3) * Mm + t];
        s_acc[t] = 0.f;
        __syncthreads();
        float invS2w  = 1.f / (__ldcg(&g_S[hd * 4 + 1]) + EPSF);
        float invS2rp = (hd > 0) ? 1.f / (__ldcg(&g_S[(hd - 1) * 4 + 3]) + EPSF) : 0.f;
        float beta_r = g_sc[(hd * 2 + 1) * 8 + 0], kn_r = g_sc[(hd * 2 + 1) * 8 + 6];
        float beta_w = g_sc[((hd + 1) * 2) * 8 + 0], kn_w = g_sc[((hd + 1) * 2) * 8 + 6];
        const float* src = (hd == 0) ? mem_in : g_mem;
        float4 racc0 = make_float4(0, 0, 0, 0), racc1 = make_float4(0, 0, 0, 0);
        float er = 0.f, ew = 0.f;
        float4 e0 = ((const float4*)s_e)[lane],  e1 = ((const float4*)s_e)[lane + 32];
        float4 a0 = ((const float4*)s_a)[lane],  a1 = ((const float4*)s_a)[lane + 32];
        float4 kr0 = ((const float4*)s_kr)[lane], kr1 = ((const float4*)s_kr)[lane + 32];
        float4 kw0 = ((const float4*)s_kw)[lane], kw1 = ((const float4*)s_kw)[lane + 32];
        {
            const float4* row = (const float4*)(src + (size_t)rbase * Mm);
            float4 m0 = row[lane], m1 = row[lane + 32];
            float wnext = g_wshw[rbase] * invS2w;
            float wpnext = (hd > 0) ? g_wshr[rbase] * invS2rp : 0.f;
            for (int k = 0; k < ROWS_W; k++) {
                int r = rbase + k;
                float4 n0, n1; float w = wnext, wp = wpnext;
                if (k + 1 < ROWS_W) {
                    const float4* nrow = (const float4*)(src + (size_t)(r + 1) * Mm);
                    n0 = nrow[lane]; n1 = nrow[lane + 32];
                    wnext = g_wshw[r + 1] * invS2w;
                    wpnext = (hd > 0) ? g_wshr[r + 1] * invS2rp : 0.f;
                }
                float4* dst = (float4*)(g_mem + (size_t)r * Mm);
                float4 nm0, nm1;
                nm0.x = m0.x * (1.f - w * e0.x) + w * a0.x;
                nm0.y = m0.y * (1.f - w * e0.y) + w * a0.y;
                nm0.z = m0.z * (1.f - w * e0.z) + w * a0.z;
                nm0.w = m0.w * (1.f - w * e0.w) + w * a0.w;
                nm1.x = m1.x * (1.f - w * e1.x) + w * a1.x;
                nm1.y = m1.y * (1.f - w * e1.y) + w * a1.y;
                nm1.z = m1.z * (1.f - w * e1.z) + w * a1.z;
                nm1.w = m1.w * (1.f - w * e1.w) + w * a1.w;
                dst[lane] = nm0; dst[lane + 32] = nm1;
                racc0.x += wp * m0.x; racc0.y += wp * m0.y; racc0.z += wp * m0.z; racc0.w += wp * m0.w;
                racc1.x += wp * m1.x; racc1.y += wp * m1.y; racc1.z += wp * m1.z; racc1.w += wp * m1.w;
                float dr = dot4(nm0, kr0) + dot4(nm1, kr1);
                float ss = dot4(nm0, nm0) + dot4(nm1, nm1);
                float dw = dot4(nm0, kw0) + dot4(nm1, kw1);
                dr = warpSum(dr); ss = warpSum(ss); dw = warpSum(dw);
                if (lane == 0) {
                    float nrm = sqrtf(ss);
                    float simr = dr / (nrm * kn_r + EPSF);
                    g_simr[r] = simr;
                    er += expf(beta_r * simr);
                    if (hd < 3) {
                        float simw = dw / (nrm * kn_w + EPSF);
                        g_simw[r] = simw;
                        ew += expf(beta_w * simw);
                    }
                }
                m0 = n0; m1 = n1;
            }
        }
        if (lane == 0) { s_red[wrp] = er; s_red[8 + wrp] = ew; }
        if (hd > 0) {
            atomicAdd(&s_acc[4 * lane + 0], racc0.x);
            atomicAdd(&s_acc[4 * lane + 1], racc0.y);
            atomicAdd(&s_acc[4 * lane + 2], racc0.z);
            atomicAdd(&s_acc[4 * lane + 3], racc0.w);
            atomicAdd(&s_acc[128 + 4 * lane + 0], racc1.x);
            atomicAdd(&s_acc[128 + 4 * lane + 1], racc1.y);
            atomicAdd(&s_acc[128 + 4 * lane + 2], racc1.z);
            atomicAdd(&s_acc[128 + 4 * lane + 3], racc1.w);
        }
        __syncthreads();
        if (t == 0) {
            float sr = 0.f, sw = 0.f;
            for (int w2 = 0; w2 < 8; w2++) { sr += s_red[w2]; sw += s_red[8 + w2]; }
            atomicAdd(&g_S[hd * 4 + 2], sr);
            if (hd < 3) atomicAdd(&g_S[(hd + 1) * 4 + 0], sw);
        }
        if (hd > 0) atomicAdd(&g_reads[(hd - 1) * Mm + t], s_acc[t]);
        gridbar(base, 3 + 2 * hd);
        addr_phase(b, t, hd, (hd < 3) ? hd + 1 : -1, prev_rw, prev_ww);
        gridbar(base, 4 + 2 * hd);
    }

    // ---- final: reads[3] = rw3 @ mem (prefetched) ----
    {
        float invS2r = 1.f / (__ldcg(&g_S[15]) + EPSF);
        s_acc[t] = 0.f;
        __syncthreads();
        float4 racc0 = make_float4(0, 0, 0, 0), racc1 = make_float4(0, 0, 0, 0);
        const float4* row = (const float4*)(g_mem + (size_t)rbase * Mm);
        float4 m0 = row[lane], m1 = row[lane + 32];
        float wnext = g_wshr[rbase] * invS2r;
        for (int k = 0; k < ROWS_W; k++) {
            float4 n0, n1; float w = wnext;
            if (k + 1 < ROWS_W) {
                const float4* nrow = (const float4*)(g_mem + (size_t)(rbase + k + 1) * Mm);
                n0 = nrow[lane]; n1 = nrow[lane + 32];
                wnext = g_wshr[rbase + k + 1] * invS2r;
            }
            racc0.x += w * m0.x; racc0.y += w * m0.y; racc0.z += w * m0.z; racc0.w += w * m0.w;
            racc1.x += w * m1.x; racc1.y += w * m1.y; racc1.z += w * m1.z; racc1.w += w * m1.w;
            m0 = n0; m1 = n1;
        }
        atomicAdd(&s_acc[4 * lane + 0], racc0.x);
        atomicAdd(&s_acc[4 * lane + 1], racc0.y);
        atomicAdd(&s_acc[4 * lane + 2], racc0.z);
        atomicAdd(&s_acc[4 * lane + 3], racc0.w);
        atomicAdd(&s_acc[128 + 4 * lane + 0], racc1.x);
        atomicAdd(&s_acc[128 + 4 * lane + 1], racc1.y);
        atomicAdd(&s_acc[128 + 4 * lane + 2], racc1.z);
        atomicAdd(&s_acc[128 + 4 * lane + 3], racc1.w);
        __syncthreads();
        atomicAdd(&g_reads[3 * Mm + t], s_acc[t]);
    }
    gridbar(base, 11);

    // ---- fused output GEMV: 4 rows per block, warp-per-row ----
    {
        for (int j = t; j < CTRLD; j += PBLK) s_rd[j] = __ldcg(&g_reads[j]);
        __syncthreads();
        if (wrp < 4) {
            int row = b * 4 + wrp;
            const float4* w4 = (const float4*)(W_out + (size_t)row * CTRLD);
            const float4* r4 = (const float4*)s_rd;
            float s = 0.f;
#pragma unroll 8
            for (int j = lane; j < 256; j += 32) s += dot4(w4[j], r4[j]);
            s = warpSum(s);
            if (lane == 0) out[row] = s + b_out[row];
        }
    }
}

// ---------------- launch -------------------------------------------------------------
extern "C" void kernel_launch(void* const* d_in, const int* in_sizes, int n_in,
                              void* d_out, int out_size) {
    const float* x          = (const float*)d_in[0];
    const float* prev_reads = (const float*)d_in[1];
    const float* prev_h     = (const float*)d_in[2];
    const float* prev_c     = (const float*)d_in[3];
    const float* memory     = (const float*)d_in[4];
    const float* prev_rw    = (const float*)d_in[5];
    const float* prev_ww    = (const float*)d_in[6];
    const float* W_ih       = (const float*)d_in[7];
    const float* W_hh       = (const float*)d_in[8];
    const float* b_lstm     = (const float*)d_in[9];
    const float* W_out      = (const float*)d_in[10];
    const float* b_out      = (const float*)d_in[11];
    const float* Ww         = (const float*)d_in[12];
    const float* bw         = (const float*)d_in[13];
    const float* Wr         = (const float*)d_in[14];
    const float* br         = (const float*)d_in[15];
    float* out = (float*)d_out;

    k_gates  <<<384, 256>>>(x, prev_reads, prev_h, prev_c, W_ih, W_hh, b_lstm);
    k_headfc <<<518, 256>>>(Ww, bw, Wr, br);
    k_persist<<<PGRID, PBLK>>>(memory, prev_rw, prev_ww, W_out, b_out, out);
}

// round 4
// speedup vs baseline: 1.0466x; 1.0466x over previous
#include <cuda_runtime.h>
#include <math.h>

#define Nn      65536
#define Mm      256
#define CTRLD   1024
#define LSTMIN  3072
#define OUTD    2048
#define EPSF    1e-8f

#define PGRID   512
#define PBLK    256
#define ROWS_B  128            // rows per block
#define ROWS_W  16             // rows per warp

// ---------------- scratch ----------------
__device__ float g_mem[(size_t)Nn * Mm];
__device__ float g_simw[Nn], g_simr[Nn];
__device__ float g_wshw[Nn], g_wshr[Nn];
__device__ float g_wn2[Nn], g_wn3[Nn];
__device__ float g_gates[3 * CTRLD];
__device__ float g_o[4 * 1036];
__device__ float g_kw[4 * Mm], g_kr[4 * Mm], g_e[4 * Mm], g_a[4 * Mm];
__device__ float g_sc[80];
__device__ float g_S[32];
__device__ float g_reads[4 * Mm];
__device__ unsigned long long g_barcnt;

// ---------------- helpers ----------------
__device__ __forceinline__ float warpSum(float v) {
#pragma unroll
    for (int o = 16; o; o >>= 1) v += __shfl_down_sync(0xffffffffu, v, o);
    return v;
}
__device__ __forceinline__ float blockSumB(float v) {   // broadcast to all threads
    __shared__ float sh[8];
    int lane = threadIdx.x & 31, wid = threadIdx.x >> 5;
    v = warpSum(v);
    if (lane == 0) sh[wid] = v;
    __syncthreads();
    float s = sh[0] + sh[1] + sh[2] + sh[3] + sh[4] + sh[5] + sh[6] + sh[7];
    __syncthreads();
    return s;
}
__device__ __forceinline__ float sigmoidf(float x) { return 1.f / (1.f + expf(-x)); }
__device__ __forceinline__ float softplusf(float x) {
    return x > 0.f ? x + log1pf(expf(-x)) : log1pf(expf(x));
}
__device__ __forceinline__ float dot4(float4 a, float4 b) {
    return a.x * b.x + a.y * b.y + a.z * b.z + a.w * b.w;
}
__device__ __forceinline__ float4 apply4(float4 m, float w, float4 e, float4 a) {
    float4 r;
    r.x = m.x * (1.f - w * e.x) + w * a.x;
    r.y = m.y * (1.f - w * e.y) + w * a.y;
    r.z = m.z * (1.f - w * e.z) + w * a.z;
    r.w = m.w * (1.f - w * e.w) + w * a.w;
    return r;
}
__device__ __forceinline__ void gridbar(int idx) {
    __syncthreads();
    if (threadIdx.x == 0) {
        __threadfence();
        atomicAdd(&g_barcnt, 1ULL);
        unsigned long long target = (unsigned long long)idx * PGRID;
        while (*(volatile unsigned long long*)&g_barcnt < target) __nanosleep(32);
        __threadfence();
    }
    __syncthreads();
}

// ---------------- init (zero barrier counter + accumulators) ----------------
__global__ void k_init() {
    int t = threadIdx.x;
    if (t == 0) g_barcnt = 0ULL;
    if (t < 32) g_S[t] = 0.f;
    g_reads[t] = 0.f;              // blockDim = 1024
}

// ---------------- addressing phase ----------------
__device__ __forceinline__ void addr_phase(int b, int t, int hr, int hw,
                                           const float* __restrict__ prev_rw,
                                           const float* __restrict__ prev_ww,
                                           float* s_red) {
    float sumr = 0.f, sumw = 0.f;
    if (t < ROWS_B) {
        int i = b * ROWS_B + t;
        int ip = (i + 1) & (Nn - 1), im = (i - 1) & (Nn - 1);
        if (hr >= 0) {
            const float* sc = g_sc + (hr * 2 + 1) * 8;
            float beta = __ldcg(&sc[0]), gg = __ldcg(&sc[1]);
            float c0 = __ldcg(&sc[2]), c1 = __ldcg(&sc[3]), c2 = __ldcg(&sc[4]);
            float gamma = __ldcg(&sc[5]);
            float gS = gg / __ldcg(&g_S[hr * 4 + 2]);
            float om = 1.f - gg;
            const float* pw = prev_rw + (size_t)hr * Nn;
            float wgp = gS * expf(beta * __ldcg(&g_simr[ip])) + om * pw[ip];
            float wgc = gS * expf(beta * __ldcg(&g_simr[i]))  + om * pw[i];
            float wgm = gS * expf(beta * __ldcg(&g_simr[im])) + om * pw[im];
            float ws = c0 * wgp + c1 * wgc + c2 * wgm;
            float wsh = powf(fmaxf(ws, 1e-12f), gamma);
            g_wshr[i] = wsh; sumr = wsh;
        }
        if (hw >= 0) {
            const float* sc = g_sc + (hw * 2) * 8;
            float beta = __ldcg(&sc[0]), gg = __ldcg(&sc[1]);
            float c0 = __ldcg(&sc[2]), c1 = __ldcg(&sc[3]), c2 = __ldcg(&sc[4]);
            float gamma = __ldcg(&sc[5]);
            float gS = gg / __ldcg(&g_S[hw * 4 + 0]);
            float om = 1.f - gg;
            const float* pw = prev_ww + (size_t)hw * Nn;
            float wgp = gS * expf(beta * __ldcg(&g_simw[ip])) + om * pw[ip];
            float wgc = gS * expf(beta * __ldcg(&g_simw[i]))  + om * pw[i];
            float wgm = gS * expf(beta * __ldcg(&g_simw[im])) + om * pw[im];
            float ws = c0 * wgp + c1 * wgc + c2 * wgm;
            float wsh = powf(fmaxf(ws, 1e-12f), gamma);
            g_wshw[i] = wsh; sumw = wsh;
        }
    }
    float sr = blockSumB(sumr);
    float sw = blockSumB(sumw);
    if (t == 0) {
        if (hr >= 0) atomicAdd(&g_S[hr * 4 + 3], sr);
        if (hw >= 0) atomicAdd(&g_S[hw * 4 + 1], sw);
    }
}

// ---------------- the one persistent kernel ----------------
__global__ void __launch_bounds__(PBLK, 4) k_all(
    const float* __restrict__ x, const float* __restrict__ prev_reads,
    const float* __restrict__ prev_h, const float* __restrict__ prev_c,
    const float* __restrict__ mem_in,
    const float* __restrict__ prev_rw, const float* __restrict__ prev_ww,
    const float* __restrict__ W_ih, const float* __restrict__ W_hh,
    const float* __restrict__ b_lstm,
    const float* __restrict__ W_out, const float* __restrict__ b_out,
    const float* __restrict__ Ww, const float* __restrict__ bw,
    const float* __restrict__ Wr, const float* __restrict__ br,
    float* __restrict__ out) {
    __shared__ float s_buf[4096];
    __shared__ float s_red[16];
    const int b = blockIdx.x, t = threadIdx.x, lane = t & 31, wrp = t >> 5;
    const int rbase = b * ROWS_B + wrp * ROWS_W;

    // ===== phase 1: LSTM gates GEMV (warps 0-5) + mem0 L2 prefetch (warps 6-7) =====
    {
        float4* si4 = (float4*)s_buf;
        for (int j = t; j < 512; j += PBLK) si4[j] = ((const float4*)x)[j];
        si4[512 + t] = ((const float4*)prev_reads)[t];
        si4[768 + t] = ((const float4*)prev_h)[t];
        __syncthreads();
        if (wrp < 6) {
            int row = b * 6 + wrp;                 // 0..3071
            const float4* wa = (const float4*)(W_ih + (size_t)row * LSTMIN);
            const float4* wh = (const float4*)(W_hh + (size_t)row * CTRLD);
            float s = 0.f;
#pragma unroll 8
            for (int j = lane; j < 768; j += 32) s += dot4(wa[j], si4[j]);
#pragma unroll 8
            for (int j = lane; j < 256; j += 32) s += dot4(wh[j], si4[768 + j]);
            s = warpSum(s);
            if (lane == 0) g_gates[row] = s + b_lstm[row];
        } else {
            int pw = b * 2 + (wrp - 6);            // 0..1023, 64KB chunk each
            const float4* p = (const float4*)mem_in + (size_t)pw * 4096;
            float acc = 0.f;
#pragma unroll 8
            for (int i = lane; i < 4096; i += 32) { float4 v = __ldcg(p + i); acc += v.x + v.w; }
            if (acc == -1.2345e+37f) g_sc[79] = acc;   // never true; defeats DCE
        }
    }
    gridbar(1);

    // ===== phase 2: ctrl (per-block, redundant) + head FC GEMV =====
    {
        for (int j = t; j < CTRLD; j += PBLK) {
            float ig = __ldcg(&g_gates[j]);
            float fg = __ldcg(&g_gates[CTRLD + j]);
            float gg = __ldcg(&g_gates[2 * CTRLD + j]);
            s_buf[j] = sigmoidf(fg) * prev_c[j] + sigmoidf(ig) * tanhf(gg);
        }
        __syncthreads();
        const float4* c4 = (const float4*)s_buf;
        int wg = b * 8 + wrp;                      // 0..4095
        for (int pass = 0; pass < 2; pass++) {
            int row = (pass == 0) ? wg : (4096 + wg);
            if (row < 4144) {
                int hd = row / 1036, k = row % 1036;
                const float* wrow; float bias;
                if (k < 774) { wrow = Ww + ((size_t)hd * 774 + k) * CTRLD; bias = bw[hd * 774 + k]; }
                else { int kk = k - 774; wrow = Wr + ((size_t)hd * 262 + kk) * CTRLD; bias = br[hd * 262 + kk]; }
                const float4* w4 = (const float4*)wrow;
                float s = 0.f;
#pragma unroll 8
                for (int j = lane; j < 256; j += 32) s += dot4(w4[j], c4[j]);
                s = warpSum(s);
                if (lane == 0) g_o[row] = s + bias;
            }
        }
    }
    gridbar(2);

    // ===== phase 3: derive (blocks 0-7, global) + local head0-write key + pass0 =====
    {
        if (b < 8) {
            int hh = b >> 1, role = b & 1;
            const float* o = g_o + hh * 1036 + (role ? 774 : 0);
            float kv = tanhf(__ldcg(&o[t]));
            (role ? g_kr : g_kw)[hh * Mm + t] = kv;
            if (!role) {
                g_e[hh * Mm + t] = sigmoidf(__ldcg(&o[262 + t]));
                g_a[hh * Mm + t] = tanhf(__ldcg(&o[518 + t]));
            }
            float ss = blockSumB(kv * kv);
            if (t == 0) {
                float* sc = g_sc + b * 8;
                sc[0] = softplusf(__ldcg(&o[256]));
                sc[1] = sigmoidf(__ldcg(&o[257]));
                float s0 = __ldcg(&o[258]), s1 = __ldcg(&o[259]), s2 = __ldcg(&o[260]);
                float mx = fmaxf(s0, fmaxf(s1, s2));
                float e0 = expf(s0 - mx), e1 = expf(s1 - mx), e2 = expf(s2 - mx);
                float es = e0 + e1 + e2;
                sc[2] = e0 / es; sc[3] = e1 / es; sc[4] = e2 / es;
                sc[5] = 1.f + softplusf(__ldcg(&o[261]));
                sc[6] = sqrtf(ss);
            }
        }
        // local head-0 write key (bit-identical to derive's)
        float kv = tanhf(__ldcg(&g_o[t]));
        s_buf[t] = kv;
        float kn = sqrtf(blockSumB(kv * kv));
        float beta0 = softplusf(__ldcg(&g_o[256]));
        __syncthreads();
        float4 k0 = ((const float4*)s_buf)[lane], k1 = ((const float4*)s_buf)[lane + 32];
        float ess = 0.f;
        for (int k = 0; k < ROWS_W; k++) {
            int r = rbase + k;
            const float4* row = (const float4*)(mem_in + (size_t)r * Mm);
            float4 m0 = row[lane], m1 = row[lane + 32];
            float dot = dot4(m0, k0) + dot4(m1, k1);
            float ss2 = dot4(m0, m0) + dot4(m1, m1);
            dot = warpSum(dot); ss2 = warpSum(ss2);
            if (lane == 0) {
                float sim = dot / (sqrtf(ss2) * kn + EPSF);
                g_simw[r] = sim;
                ess += expf(beta0 * sim);
            }
        }
        if (lane == 0) s_red[wrp] = ess;
        __syncthreads();
        if (t == 0) {
            float s = 0.f;
            for (int w = 0; w < 8; w++) s += s_red[w];
            atomicAdd(&g_S[0], s);
        }
    }
    gridbar(3);
    addr_phase(b, t, -1, 0, prev_rw, prev_ww, s_red);
    gridbar(4);

    // ===== U0: mem0 -> write mem1; sims kr0 / kw1 =====
    {
        float invS2w = 1.f / (__ldcg(&g_S[1]) + EPSF);
        float beta_r = __ldcg(&g_sc[1 * 8 + 0]), kn_r = __ldcg(&g_sc[1 * 8 + 6]);
        float beta_w = __ldcg(&g_sc[2 * 8 + 0]), kn_w = __ldcg(&g_sc[2 * 8 + 6]);
        float4 e0 = __ldcg((const float4*)g_e + lane),        e1 = __ldcg((const float4*)g_e + lane + 32);
        float4 a0 = __ldcg((const float4*)g_a + lane),        a1 = __ldcg((const float4*)g_a + lane + 32);
        float4 kr0 = __ldcg((const float4*)g_kr + lane),      kr1 = __ldcg((const float4*)g_kr + lane + 32);
        float4 kw0 = __ldcg((const float4*)(g_kw + Mm) + lane), kw1 = __ldcg((const float4*)(g_kw + Mm) + lane + 32);
        float er = 0.f, ew = 0.f;
        for (int k = 0; k < ROWS_W; k++) {
            int r = rbase + k;
            float w = g_wshw[r] * invS2w;
            const float4* row = (const float4*)(mem_in + (size_t)r * Mm);
            float4* dst = (float4*)(g_mem + (size_t)r * Mm);
            float4 m0 = row[lane], m1 = row[lane + 32];
            float4 n0 = apply4(m0, w, e0, a0), n1 = apply4(m1, w, e1, a1);
            dst[lane] = n0; dst[lane + 32] = n1;
            float dr = dot4(n0, kr0) + dot4(n1, kr1);
            float ss = dot4(n0, n0) + dot4(n1, n1);
            float dw = dot4(n0, kw0) + dot4(n1, kw1);
            dr = warpSum(dr); ss = warpSum(ss); dw = warpSum(dw);
            if (lane == 0) {
                float nrm = sqrtf(ss);
                float simr = dr / (nrm * kn_r + EPSF); g_simr[r] = simr; er += expf(beta_r * simr);
                float simw = dw / (nrm * kn_w + EPSF); g_simw[r] = simw; ew += expf(beta_w * simw);
            }
        }
        if (lane == 0) { s_red[wrp] = er; s_red[8 + wrp] = ew; }
        __syncthreads();
        if (t == 0) {
            float sr = 0.f, sw = 0.f;
            for (int w2 = 0; w2 < 8; w2++) { sr += s_red[w2]; sw += s_red[8 + w2]; }
            atomicAdd(&g_S[2], sr); atomicAdd(&g_S[4], sw);
        }
    }
    gridbar(5);
    addr_phase(b, t, 0, 1, prev_rw, prev_ww, s_red);
    gridbar(6);

    // ===== U1: mem1 -> write mem2; reads[0]; sims kr1 / kw2 =====
    {
        float invS2w = 1.f / (__ldcg(&g_S[5]) + EPSF);
        float invS2r = 1.f / (__ldcg(&g_S[3]) + EPSF);
        float beta_r = __ldcg(&g_sc[3 * 8 + 0]), kn_r = __ldcg(&g_sc[3 * 8 + 6]);
        float beta_w = __ldcg(&g_sc[4 * 8 + 0]), kn_w = __ldcg(&g_sc[4 * 8 + 6]);
        float4 e0 = __ldcg((const float4*)(g_e + Mm) + lane),  e1 = __ldcg((const float4*)(g_e + Mm) + lane + 32);
        float4 a0 = __ldcg((const float4*)(g_a + Mm) + lane),  a1 = __ldcg((const float4*)(g_a + Mm) + lane + 32);
        float4 kr0 = __ldcg((const float4*)(g_kr + Mm) + lane), kr1 = __ldcg((const float4*)(g_kr + Mm) + lane + 32);
        float4 kw0 = __ldcg((const float4*)(g_kw + 2 * Mm) + lane), kw1 = __ldcg((const float4*)(g_kw + 2 * Mm) + lane + 32);
        float4 racc0 = make_float4(0, 0, 0, 0), racc1 = make_float4(0, 0, 0, 0);
        s_buf[t] = 0.f;
        __syncthreads();
        float er = 0.f, ew = 0.f;
        for (int k = 0; k < ROWS_W; k++) {
            int r = rbase + k;
            float w = g_wshw[r] * invS2w;
            float wp = g_wshr[r] * invS2r;
            const float4* row = (const float4*)(g_mem + (size_t)r * Mm);
            float4 m0 = row[lane], m1 = row[lane + 32];
            racc0.x += wp * m0.x; racc0.y += wp * m0.y; racc0.z += wp * m0.z; racc0.w += wp * m0.w;
            racc1.x += wp * m1.x; racc1.y += wp * m1.y; racc1.z += wp * m1.z; racc1.w += wp * m1.w;
            float4 n0 = apply4(m0, w, e0, a0), n1 = apply4(m1, w, e1, a1);
            float4* dst = (float4*)(g_mem + (size_t)r * Mm);
            dst[lane] = n0; dst[lane + 32] = n1;
            float dr = dot4(n0, kr0) + dot4(n1, kr1);
            float ss = dot4(n0, n0) + dot4(n1, n1);
            float dw = dot4(n0, kw0) + dot4(n1, kw1);
            dr = warpSum(dr); ss = warpSum(ss); dw = warpSum(dw);
            if (lane == 0) {
                float nrm = sqrtf(ss);
                float simr = dr / (nrm * kn_r + EPSF); g_simr[r] = simr; er += expf(beta_r * simr);
                float simw = dw / (nrm * kn_w + EPSF); g_simw[r] = simw; ew += expf(beta_w * simw);
            }
        }
        if (lane == 0) { s_red[wrp] = er; s_red[8 + wrp] = ew; }
        atomicAdd(&s_buf[4 * lane + 0], racc0.x); atomicAdd(&s_buf[4 * lane + 1], racc0.y);
        atomicAdd(&s_buf[4 * lane + 2], racc0.z); atomicAdd(&s_buf[4 * lane + 3], racc0.w);
        atomicAdd(&s_buf[128 + 4 * lane + 0], racc1.x); atomicAdd(&s_buf[128 + 4 * lane + 1], racc1.y);
        atomicAdd(&s_buf[128 + 4 * lane + 2], racc1.z); atomicAdd(&s_buf[128 + 4 * lane + 3], racc1.w);
        __syncthreads();
        if (t == 0) {
            float sr = 0.f, sw = 0.f;
            for (int w2 = 0; w2 < 8; w2++) { sr += s_red[w2]; sw += s_red[8 + w2]; }
            atomicAdd(&g_S[6], sr); atomicAdd(&g_S[8], sw);
        }
        atomicAdd(&g_reads[0 * Mm + t], s_buf[t]);
    }
    gridbar(7);
    addr_phase(b, t, 1, 2, prev_rw, prev_ww, s_red);
    gridbar(8);

    // ===== U2: read mem2 (no write); reads[1]; w2 applied on the fly; sims kr2 / kw3 =====
    {
        float invS2w = 1.f / (__ldcg(&g_S[9]) + EPSF);
        float invS2r = 1.f / (__ldcg(&g_S[7]) + EPSF);
        float beta_r = __ldcg(&g_sc[5 * 8 + 0]), kn_r = __ldcg(&g_sc[5 * 8 + 6]);
        float beta_w = __ldcg(&g_sc[6 * 8 + 0]), kn_w = __ldcg(&g_sc[6 * 8 + 6]);
        float4 e0 = __ldcg((const float4*)(g_e + 2 * Mm) + lane),  e1 = __ldcg((const float4*)(g_e + 2 * Mm) + lane + 32);
        float4 a0 = __ldcg((const float4*)(g_a + 2 * Mm) + lane),  a1 = __ldcg((const float4*)(g_a + 2 * Mm) + lane + 32);
        float4 kr0 = __ldcg((const float4*)(g_kr + 2 * Mm) + lane), kr1 = __ldcg((const float4*)(g_kr + 2 * Mm) + lane + 32);
        float4 kw0 = __ldcg((const float4*)(g_kw + 3 * Mm) + lane), kw1 = __ldcg((const float4*)(g_kw + 3 * Mm) + lane + 32);
        float4 racc0 = make_float4(0, 0, 0, 0), racc1 = make_float4(0, 0, 0, 0);
        s_buf[t] = 0.f;
        __syncthreads();
        float er = 0.f, ew = 0.f;
        for (int k = 0; k < ROWS_W; k++) {
            int r = rbase + k;
            float w = g_wshw[r] * invS2w;
            if (lane == 0) g_wn2[r] = w;
            float wp = g_wshr[r] * invS2r;
            const float4* row = (const float4*)(g_mem + (size_t)r * Mm);
            float4 m0 = row[lane], m1 = row[lane + 32];
            racc0.x += wp * m0.x; racc0.y += wp * m0.y; racc0.z += wp * m0.z; racc0.w += wp * m0.w;
            racc1.x += wp * m1.x; racc1.y += wp * m1.y; racc1.z += wp * m1.z; racc1.w += wp * m1.w;
            float4 n0 = apply4(m0, w, e0, a0), n1 = apply4(m1, w, e1, a1);
            float dr = dot4(n0, kr0) + dot4(n1, kr1);
            float ss = dot4(n0, n0) + dot4(n1, n1);
            float dw = dot4(n0, kw0) + dot4(n1, kw1);
            dr = warpSum(dr); ss = warpSum(ss); dw = warpSum(dw);
            if (lane == 0) {
                float nrm = sqrtf(ss);
                float simr = dr / (nrm * kn_r + EPSF); g_simr[r] = simr; er += expf(beta_r * simr);
                float simw = dw / (nrm * kn_w + EPSF); g_simw[r] = simw; ew += expf(beta_w * simw);
            }
        }
        if (lane == 0) { s_red[wrp] = er; s_red[8 + wrp] = ew; }
        atomicAdd(&s_buf[4 * lane + 0], racc0.x); atomicAdd(&s_buf[4 * lane + 1], racc0.y);
        atomicAdd(&s_buf[4 * lane + 2], racc0.z); atomicAdd(&s_buf[4 * lane + 3], racc0.w);
        atomicAdd(&s_buf[128 + 4 * lane + 0], racc1.x); atomicAdd(&s_buf[128 + 4 * lane + 1], racc1.y);
        atomicAdd(&s_buf[128 + 4 * lane + 2], racc1.z); atomicAdd(&s_buf[128 + 4 * lane + 3], racc1.w);
        __syncthreads();
        if (t == 0) {
            float sr = 0.f, sw = 0.f;
            for (int w2 = 0; w2 < 8; w2++) { sr += s_red[w2]; sw += s_red[8 + w2]; }
            atomicAdd(&g_S[10], sr); atomicAdd(&g_S[12], sw);
        }
        atomicAdd(&g_reads[1 * Mm + t], s_buf[t]);
    }
    gridbar(9);
    addr_phase(b, t, 2, 3, prev_rw, prev_ww, s_red);
    gridbar(10);

    // ===== U3: read mem2 (no write); apply w2 then w3; reads[2]; sims kr3 =====
    {
        float invS2w = 1.f / (__ldcg(&g_S[13]) + EPSF);
        float invS2r = 1.f / (__ldcg(&g_S[11]) + EPSF);
        float beta_r = __ldcg(&g_sc[7 * 8 + 0]), kn_r = __ldcg(&g_sc[7 * 8 + 6]);
        float4 e20 = __ldcg((const float4*)(g_e + 2 * Mm) + lane), e21 = __ldcg((const float4*)(g_e + 2 * Mm) + lane + 32);
        float4 a20 = __ldcg((const float4*)(g_a + 2 * Mm) + lane), a21 = __ldcg((const float4*)(g_a + 2 * Mm) + lane + 32);
        float4 e30 = __ldcg((const float4*)(g_e + 3 * Mm) + lane), e31 = __ldcg((const float4*)(g_e + 3 * Mm) + lane + 32);
        float4 a30 = __ldcg((const float4*)(g_a + 3 * Mm) + lane), a31 = __ldcg((const float4*)(g_a + 3 * Mm) + lane + 32);
        float4 kr0 = __ldcg((const float4*)(g_kr + 3 * Mm) + lane), kr1 = __ldcg((const float4*)(g_kr + 3 * Mm) + lane + 32);
        float4 racc0 = make_float4(0, 0, 0, 0), racc1 = make_float4(0, 0, 0, 0);
        s_buf[t] = 0.f;
        __syncthreads();
        float er = 0.f;
        for (int k = 0; k < ROWS_W; k++) {
            int r = rbase + k;
            float w2 = g_wn2[r];
            float w3 = g_wshw[r] * invS2w;
            if (lane == 0) g_wn3[r] = w3;
            float wp = g_wshr[r] * invS2r;
            const float4* row = (const float4*)(g_mem + (size_t)r * Mm);
            float4 m0 = row[lane], m1 = row[lane + 32];
            m0 = apply4(m0, w2, e20, a20); m1 = apply4(m1, w2, e21, a21);   // mem3
            racc0.x += wp * m0.x; racc0.y += wp * m0.y; racc0.z += wp * m0.z; racc0.w += wp * m0.w;
            racc1.x += wp * m1.x; racc1.y += wp * m1.y; racc1.z += wp * m1.z; racc1.w += wp * m1.w;
            float4 n0 = apply4(m0, w3, e30, a30), n1 = apply4(m1, w3, e31, a31);   // mem4
            float dr = dot4(n0, kr0) + dot4(n1, kr1);
            float ss = dot4(n0, n0) + dot4(n1, n1);
            dr = warpSum(dr); ss = warpSum(ss);
            if (lane == 0) {
                float simr = dr / (sqrtf(ss) * kn_r + EPSF);
                g_simr[r] = simr; er += expf(beta_r * simr);
            }
        }
        if (lane == 0) s_red[wrp] = er;
        atomicAdd(&s_buf[4 * lane + 0], racc0.x); atomicAdd(&s_buf[4 * lane + 1], racc0.y);
        atomicAdd(&s_buf[4 * lane + 2], racc0.z); atomicAdd(&s_buf[4 * lane + 3], racc0.w);
        atomicAdd(&s_buf[128 + 4 * lane + 0], racc1.x); atomicAdd(&s_buf[128 + 4 * lane + 1], racc1.y);
        atomicAdd(&s_buf[128 + 4 * lane + 2], racc1.z); atomicAdd(&s_buf[128 + 4 * lane + 3], racc1.w);
        __syncthreads();
        if (t == 0) {
            float sr = 0.f;
            for (int w2 = 0; w2 < 8; w2++) sr += s_red[w2];
            atomicAdd(&g_S[14], sr);
        }
        atomicAdd(&g_reads[2 * Mm + t], s_buf[t]);
    }
    gridbar(11);
    addr_phase(b, t, 3, -1, prev_rw, prev_ww, s_red);
    gridbar(12);

    // ===== FINAL: reads[3] on mem4 = apply(w2, w3) over mem2 =====
    {
        float invS2r = 1.f / (__ldcg(&g_S[15]) + EPSF);
        float4 e20 = __ldcg((const float4*)(g_e + 2 * Mm) + lane), e21 = __ldcg((const float4*)(g_e + 2 * Mm) + lane + 32);
        float4 a20 = __ldcg((const float4*)(g_a + 2 * Mm) + lane), a21 = __ldcg((const float4*)(g_a + 2 * Mm) + lane + 32);
        float4 e30 = __ldcg((const float4*)(g_e + 3 * Mm) + lane), e31 = __ldcg((const float4*)(g_e + 3 * Mm) + lane + 32);
        float4 a30 = __ldcg((const float4*)(g_a + 3 * Mm) + lane), a31 = __ldcg((const float4*)(g_a + 3 * Mm) + lane + 32);
        float4 racc0 = make_float4(0, 0, 0, 0), racc1 = make_float4(0, 0, 0, 0);
        s_buf[t] = 0.f;
        __syncthreads();
        for (int k = 0; k < ROWS_W; k++) {
            int r = rbase + k;
            float w2 = g_wn2[r], w3 = g_wn3[r];
            float wr = g_wshr[r] * invS2r;
            const float4* row = (const float4*)(g_mem + (size_t)r * Mm);
            float4 m0 = row[lane], m1 = row[lane + 32];
            m0 = apply4(m0, w2, e20, a20); m1 = apply4(m1, w2, e21, a21);
            m0 = apply4(m0, w3, e30, a30); m1 = apply4(m1, w3, e31, a31);
            racc0.x += wr * m0.x; racc0.y += wr * m0.y; racc0.z += wr * m0.z; racc0.w += wr * m0.w;
            racc1.x += wr * m1.x; racc1.y += wr * m1.y; racc1.z += wr * m1.z; racc1.w += wr * m1.w;
        }
        atomicAdd(&s_buf[4 * lane + 0], racc0.x); atomicAdd(&s_buf[4 * lane + 1], racc0.y);
        atomicAdd(&s_buf[4 * lane + 2], racc0.z); atomicAdd(&s_buf[4 * lane + 3], racc0.w);
        atomicAdd(&s_buf[128 + 4 * lane + 0], racc1.x); atomicAdd(&s_buf[128 + 4 * lane + 1], racc1.y);
        atomicAdd(&s_buf[128 + 4 * lane + 2], racc1.z); atomicAdd(&s_buf[128 + 4 * lane + 3], racc1.w);
        __syncthreads();
        atomicAdd(&g_reads[3 * Mm + t], s_buf[t]);
    }
    gridbar(13);

    // ===== OUT: 4 rows/block, warp-per-row =====
    {
        for (int j = t; j < CTRLD; j += PBLK) s_buf[j] = __ldcg(&g_reads[j]);
        __syncthreads();
        if (wrp < 4) {
            int row = b * 4 + wrp;
            const float4* w4 = (const float4*)(W_out + (size_t)row * CTRLD);
            const float4* r4 = (const float4*)s_buf;
            float s = 0.f;
#pragma unroll 8
            for (int j = lane; j < 256; j += 32) s += dot4(w4[j], r4[j]);
            s = warpSum(s);
            if (lane == 0) out[row] = s + b_out[row];
        }
    }
}

// ---------------- launch ----------------
extern "C" void kernel_launch(void* const* d_in, const int* in_sizes, int n_in,
                              void* d_out, int out_size) {
    const float* x          = (const float*)d_in[0];
    const float* prev_reads = (const float*)d_in[1];
    const float* prev_h     = (const float*)d_in[2];
    const float* prev_c     = (const float*)d_in[3];
    const float* memory     = (const float*)d_in[4];
    const float* prev_rw    = (const float*)d_in[5];
    const float* prev_ww    = (const float*)d_in[6];
    const float* W_ih       = (const float*)d_in[7];
    const float* W_hh       = (const float*)d_in[8];
    const float* b_lstm     = (const float*)d_in[9];
    const float* W_out      = (const float*)d_in[10];
    const float* b_out      = (const float*)d_in[11];
    const float* Ww         = (const float*)d_in[12];
    const float* bw         = (const float*)d_in[13];
    const float* Wr         = (const float*)d_in[14];
    const float* br         = (const float*)d_in[15];
    float* out = (float*)d_out;

    k_init<<<1, 1024>>>();
    k_all<<<PGRID, PBLK>>>(x, prev_reads, prev_h, prev_c, memory, prev_rw, prev_ww,
                           W_ih, W_hh, b_lstm, W_out, b_out, Ww, bw, Wr, br, out);
}